// round 1
// baseline (speedup 1.0000x reference)
#include <cuda_runtime.h>

#define G_N 8192
#define IMG_W 512
#define IMG_H 512
#define TILE 16
#define TPB 256
#define NWARP (TPB / 32)

// Sorted (by depth) gaussian data, gathered once per launch.
__device__ float2 d_mean[G_N];   // mx, my
__device__ float4 d_cabc[G_N];   // a, b, c, opacity
__device__ float4 d_col [G_N];   // r, g, b, pad
__device__ float4 d_bbox[G_N];   // x0, y0, x1, y1 (conservative footprint)

// ---------------------------------------------------------------------------
// Kernel 1: stable rank-sort by depth + gather into sorted SoA + bbox compute.
// Grid: 32 blocks x 256 threads = 8192 threads, one per gaussian.
// Rank via brute-force count against composite key (depth_bits, index):
// reproduces jnp.argsort(stable=True) exactly (positive floats -> monotone bits).
// ---------------------------------------------------------------------------
__global__ __launch_bounds__(TPB) void sort_gather_kernel(
    const float* __restrict__ means2d,
    const float* __restrict__ conics,
    const float* __restrict__ colors,
    const float* __restrict__ opac,
    const float* __restrict__ depths)
{
    __shared__ unsigned s_bits[G_N];   // 32 KB
    const int tid = threadIdx.x;
    for (int j = tid; j < G_N; j += TPB)
        s_bits[j] = __float_as_uint(depths[j]);   // depths > 0 -> order-preserving
    __syncthreads();

    const int i = blockIdx.x * TPB + tid;
    const unsigned bi = s_bits[i];
    int r = 0;
#pragma unroll 8
    for (int j = 0; j < G_N; ++j) {
        const unsigned bj = s_bits[j];
        r += (bj < bi) || ((bj == bi) && (j < i));
    }

    const float mx = means2d[2 * i];
    const float my = means2d[2 * i + 1];
    const float a  = conics[3 * i];
    const float b  = conics[3 * i + 1];
    const float c  = conics[3 * i + 2];
    const float op = opac[i];

    d_mean[r] = make_float2(mx, my);
    d_cabc[r] = make_float4(a, b, c, op);
    d_col[r]  = make_float4(colors[3 * i], colors[3 * i + 1], colors[3 * i + 2], 0.0f);

    // Conservative footprint: alpha = op*exp(-sigma) >= 1/255  <=>  sigma <= ln(255*op).
    // sigma = 0.5*x^T C x ; ellipse bbox half-widths = sqrt(2*t*Sigma_xx/yy),
    // Sigma = inv(C) = [c,-b;-b,a]/det.
    const float t   = logf(op * 255.0f);
    const float det = a * c - b * b;
    float4 bb;
    if (t > 0.0f && det > 0.0f) {
        const float rx = sqrtf(fmaxf(0.0f, 2.0f * t * c / det)) * 1.001f + 0.01f;
        const float ry = sqrtf(fmaxf(0.0f, 2.0f * t * a / det)) * 1.001f + 0.01f;
        bb = make_float4(mx - rx, my - ry, mx + rx, my + ry);
    } else {
        bb = make_float4(1e9f, 1e9f, -1e9f, -1e9f);   // never intersects
    }
    d_bbox[r] = bb;
}

// ---------------------------------------------------------------------------
// Kernel 2: tile raster. One 16x16 tile per block (grid 32x32), 256 threads
// = 1 pixel/thread. Per 256-gaussian chunk: bbox-cull, order-preserving
// compaction into shared, then sequential front-to-back compositing with
// exact early exit at T < 1e-4 (weights past that point are exactly zero
// in the reference). Tile-wide break when all pixels are done.
// ---------------------------------------------------------------------------
__global__ __launch_bounds__(TPB) void raster_kernel(float* __restrict__ out)
{
    const int tileX = blockIdx.x, tileY = blockIdx.y;
    const int tid   = threadIdx.x;
    const int lx    = tid & (TILE - 1);
    const int ly    = tid / TILE;
    const float px  = (float)(tileX * TILE + lx) + 0.5f;
    const float py  = (float)(tileY * TILE + ly) + 0.5f;
    const float tx0 = (float)(tileX * TILE);
    const float tx1 = tx0 + (float)TILE;
    const float ty0 = (float)(tileY * TILE);
    const float ty1 = ty0 + (float)TILE;

    __shared__ float2 s_xy[TPB];
    __shared__ float4 s_co[TPB];
    __shared__ float4 s_cl[TPB];
    __shared__ int    s_wcnt[NWARP];

    const int warp = tid >> 5, lane = tid & 31;

    float T = 1.0f;
    float accR = 0.0f, accG = 0.0f, accB = 0.0f;
    bool done = false;

    for (int base = 0; base < G_N; base += TPB) {
        const int gi = base + tid;
        const float4 bb = d_bbox[gi];
        const bool hit = (bb.x <= tx1) && (bb.z >= tx0) &&
                         (bb.y <= ty1) && (bb.w >= ty0);

        const unsigned m = __ballot_sync(0xffffffffu, hit);
        if (lane == 0) s_wcnt[warp] = __popc(m);
        __syncthreads();

        int ofs = 0, cnt = 0;
#pragma unroll
        for (int w = 0; w < NWARP; ++w) {
            const int c = s_wcnt[w];
            ofs += (w < warp) ? c : 0;
            cnt += c;
        }

        if (hit) {
            const int slot = ofs + __popc(m & ((1u << lane) - 1u));
            s_xy[slot] = d_mean[gi];
            s_co[slot] = d_cabc[gi];
            s_cl[slot] = d_col[gi];
        }
        __syncthreads();

        if (!done) {
            for (int j = 0; j < cnt; ++j) {
                const float2 xy = s_xy[j];
                const float4 co = s_co[j];
                const float dx = px - xy.x;
                const float dy = py - xy.y;
                const float sigma = 0.5f * (co.x * dx * dx + co.z * dy * dy)
                                  + co.y * dx * dy;
                float alpha = co.w * __expf(-sigma);
                if (sigma >= 0.0f && alpha >= (1.0f / 255.0f)) {
                    alpha = fminf(alpha, 0.99f);
                    const float wgt = alpha * T;
                    const float4 cl = s_cl[j];
                    accR += wgt * cl.x;
                    accG += wgt * cl.y;
                    accB += wgt * cl.z;
                    T *= (1.0f - alpha);
                    if (T < 1e-4f) { done = true; break; }
                }
            }
        }

        const int active = __syncthreads_count(done ? 0 : 1);
        if (active == 0) break;
    }

    const int x = tileX * TILE + lx;
    const int y = tileY * TILE + ly;
    float* o = out + ((size_t)y * IMG_W + x) * 3;
    o[0] = accR;
    o[1] = accG;
    o[2] = accB;
}

// ---------------------------------------------------------------------------
extern "C" void kernel_launch(void* const* d_in, const int* in_sizes, int n_in,
                              void* d_out, int out_size)
{
    const float* means2d   = (const float*)d_in[0];
    const float* conics    = (const float*)d_in[1];
    const float* colors    = (const float*)d_in[2];
    const float* opacities = (const float*)d_in[3];
    const float* depths    = (const float*)d_in[4];
    float* out = (float*)d_out;

    sort_gather_kernel<<<G_N / TPB, TPB>>>(means2d, conics, colors, opacities, depths);
    dim3 grid(IMG_W / TILE, IMG_H / TILE);
    raster_kernel<<<grid, TPB>>>(out);
}

// round 2
// speedup vs baseline: 1.7025x; 1.7025x over previous
#include <cuda_runtime.h>

#define G_N 8192
#define IMG_W 512
#define IMG_H 512
#define TILE 16
#define TPB 256
#define NWARP (TPB / 32)
#define SORT_WPB 8   // warps per block in sort kernel (one gaussian per warp)

// Sorted (by depth) gaussian data, raster-ready layout.
__device__ float4 d_A[G_N];      // mx, my, 0.5*a, b
__device__ float4 d_B[G_N];      // 0.5*c, sigma_max=ln(255*op), op, col.r
__device__ float2 d_C[G_N];      // col.g, col.b
__device__ float4 d_bbox[G_N];   // x0, y0, x1, y1 (conservative footprint)

// ---------------------------------------------------------------------------
// Kernel 1: stable rank-sort by depth + gather into sorted SoA + bbox compute.
// One WARP per gaussian: 1024 blocks x 8 warps = 8192 warps. Lanes split the
// 8192-key count loop (256 iters each), __reduce_add_sync gives the rank.
// Composite key (depth_bits, index) reproduces argsort(stable=True) exactly.
// ---------------------------------------------------------------------------
__global__ __launch_bounds__(TPB) void sort_gather_kernel(
    const float* __restrict__ means2d,
    const float* __restrict__ conics,
    const float* __restrict__ colors,
    const float* __restrict__ opac,
    const float* __restrict__ depths)
{
    __shared__ unsigned s_bits[G_N];   // 32 KB
    const int tid  = threadIdx.x;
    const int warp = tid >> 5, lane = tid & 31;

    for (int j = tid; j < G_N; j += TPB)
        s_bits[j] = __float_as_uint(depths[j]);   // depths > 0 -> order-preserving
    __syncthreads();

    const int i = blockIdx.x * SORT_WPB + warp;
    const unsigned ki = s_bits[i];

    int cnt = 0;
#pragma unroll 8
    for (int t = 0; t < G_N / 32; ++t) {
        const int j = t * 32 + lane;               // stride-1 across lanes: conflict-free
        const unsigned kj = s_bits[j];
        cnt += (kj < ki) || ((kj == ki) && (j < i));
    }
    const int r = __reduce_add_sync(0xffffffffu, cnt);

    if (lane == 0) {
        const float mx = means2d[2 * i];
        const float my = means2d[2 * i + 1];
        const float a  = conics[3 * i];
        const float b  = conics[3 * i + 1];
        const float c  = conics[3 * i + 2];
        const float op = opac[i];
        const float cr = colors[3 * i];
        const float cg = colors[3 * i + 1];
        const float cb = colors[3 * i + 2];

        // alpha = op*exp(-sigma) >= 1/255  <=>  sigma <= ln(255*op) = smax
        const float smax = logf(op * 255.0f);
        const float det  = a * c - b * b;

        d_A[r] = make_float4(mx, my, 0.5f * a, b);
        d_B[r] = make_float4(0.5f * c, smax, op, cr);
        d_C[r] = make_float2(cg, cb);

        // Conservative bbox of {sigma <= smax}: half-widths sqrt(2*smax*Sigma_xx/yy),
        // Sigma = inv(C) = [c,-b;-b,a]/det.
        float4 bb;
        if (smax > 0.0f && det > 0.0f) {
            const float rx = sqrtf(fmaxf(0.0f, 2.0f * smax * c / det)) * 1.001f + 0.01f;
            const float ry = sqrtf(fmaxf(0.0f, 2.0f * smax * a / det)) * 1.001f + 0.01f;
            bb = make_float4(mx - rx, my - ry, mx + rx, my + ry);
        } else {
            bb = make_float4(1e9f, 1e9f, -1e9f, -1e9f);   // never intersects
        }
        d_bbox[r] = bb;
    }
}

// ---------------------------------------------------------------------------
// Kernel 2: tile raster. 16x16 tile per block (grid 32x32), 1 px/thread.
// Per 256-gaussian chunk: bbox-cull -> order-preserving ballot compaction to
// shared -> sequential front-to-back compositing. __expf only evaluated when
// sigma is inside [0, sigma_max] (i.e. alpha would pass the 1/255 threshold).
// Exact early exit at T < 1e-4; tile-wide break via __syncthreads_count.
// ---------------------------------------------------------------------------
__global__ __launch_bounds__(TPB) void raster_kernel(float* __restrict__ out)
{
    const int tileX = blockIdx.x, tileY = blockIdx.y;
    const int tid   = threadIdx.x;
    const int lx    = tid & (TILE - 1);
    const int ly    = tid / TILE;
    const float px  = (float)(tileX * TILE + lx) + 0.5f;
    const float py  = (float)(tileY * TILE + ly) + 0.5f;
    const float tx0 = (float)(tileX * TILE);
    const float tx1 = tx0 + (float)TILE;
    const float ty0 = (float)(tileY * TILE);
    const float ty1 = ty0 + (float)TILE;

    __shared__ float4 s_A[TPB];
    __shared__ float4 s_B[TPB];
    __shared__ float2 s_C[TPB];
    __shared__ int    s_wcnt[NWARP];

    const int warp = tid >> 5, lane = tid & 31;

    float T = 1.0f;
    float accR = 0.0f, accG = 0.0f, accB = 0.0f;
    bool done = false;

    for (int base = 0; base < G_N; base += TPB) {
        const int gi = base + tid;
        const float4 bb = d_bbox[gi];
        const bool hit = (bb.x <= tx1) && (bb.z >= tx0) &&
                         (bb.y <= ty1) && (bb.w >= ty0);

        const unsigned m = __ballot_sync(0xffffffffu, hit);
        if (lane == 0) s_wcnt[warp] = __popc(m);
        __syncthreads();

        int ofs = 0, cnt = 0;
#pragma unroll
        for (int w = 0; w < NWARP; ++w) {
            const int c = s_wcnt[w];
            ofs += (w < warp) ? c : 0;
            cnt += c;
        }

        if (hit) {
            const int slot = ofs + __popc(m & ((1u << lane) - 1u));
            s_A[slot] = d_A[gi];
            s_B[slot] = d_B[gi];
            s_C[slot] = d_C[gi];
        }
        __syncthreads();

        if (!done) {
            for (int j = 0; j < cnt; ++j) {
                const float4 A = s_A[j];               // mx, my, a/2, b
                const float4 B = s_B[j];               // c/2, smax, op, col.r
                const float dx = px - A.x;
                const float dy = py - A.y;
                const float sigma = fmaf(A.z * dx, dx,
                                    fmaf(B.x * dy, dy, A.w * dx * dy));
                // Pass iff sigma in [0, smax] (<=> alpha >= 1/255 and sigma >= 0).
                if (sigma >= 0.0f && sigma <= B.y) {
                    float alpha = fminf(0.99f, B.z * __expf(-sigma));
                    const float wgt = alpha * T;
                    const float2 C = s_C[j];
                    accR += wgt * B.w;
                    accG += wgt * C.x;
                    accB += wgt * C.y;
                    T *= (1.0f - alpha);
                    if (T < 1e-4f) { done = true; break; }
                }
            }
        }

        const int active = __syncthreads_count(done ? 0 : 1);
        if (active == 0) break;
    }

    const int x = tileX * TILE + lx;
    const int y = tileY * TILE + ly;
    float* o = out + ((size_t)y * IMG_W + x) * 3;
    o[0] = accR;
    o[1] = accG;
    o[2] = accB;
}

// ---------------------------------------------------------------------------
extern "C" void kernel_launch(void* const* d_in, const int* in_sizes, int n_in,
                              void* d_out, int out_size)
{
    const float* means2d   = (const float*)d_in[0];
    const float* conics    = (const float*)d_in[1];
    const float* colors    = (const float*)d_in[2];
    const float* opacities = (const float*)d_in[3];
    const float* depths    = (const float*)d_in[4];
    float* out = (float*)d_out;

    sort_gather_kernel<<<G_N / SORT_WPB, TPB>>>(means2d, conics, colors, opacities, depths);
    dim3 grid(IMG_W / TILE, IMG_H / TILE);
    raster_kernel<<<grid, TPB>>>(out);
}

// round 3
// speedup vs baseline: 1.7242x; 1.0127x over previous
#include <cuda_runtime.h>

#define G_N 8192
#define IMG_W 512
#define IMG_H 512
#define TILE 16
#define CHUNK 256          // gaussians per cull/compact chunk
#define TPB 128            // raster threads per block (2 px/thread)
#define SORT_TPB 256
#define SORT_WPB 8         // warps per block in sort kernel (one gaussian per warp)

// Sorted (by depth) gaussian data, raster-ready layout.
__device__ float4 d_A[G_N];      // mx, my, 0.5*a, b
__device__ float4 d_B[G_N];      // 0.5*c, sigma_max=ln(255*op), op, col.r
__device__ float2 d_C[G_N];      // col.g, col.b
__device__ float4 d_bbox[G_N];   // x0, y0, x1, y1 (conservative footprint)

// ---------------------------------------------------------------------------
// Kernel 1: stable rank-sort by depth + gather + bbox. One warp per gaussian;
// each lane compares 2 keys per LDS.64. Composite key (depth_bits, index)
// reproduces argsort(stable=True) exactly (positive floats -> monotone bits).
// ---------------------------------------------------------------------------
__global__ __launch_bounds__(SORT_TPB) void sort_gather_kernel(
    const float* __restrict__ means2d,
    const float* __restrict__ conics,
    const float* __restrict__ colors,
    const float* __restrict__ opac,
    const float* __restrict__ depths)
{
    __shared__ uint2 s_bits2[G_N / 2];   // 32 KB
    const int tid  = threadIdx.x;
    const int warp = tid >> 5, lane = tid & 31;

    const uint2* dbits = (const uint2*)depths;
    for (int j = tid; j < G_N / 2; j += SORT_TPB)
        s_bits2[j] = dbits[j];
    __syncthreads();

    const int i = blockIdx.x * SORT_WPB + warp;
    const unsigned ki = ((const unsigned*)s_bits2)[i];

    int cnt = 0;
#pragma unroll 8
    for (int t = 0; t < G_N / 64; ++t) {
        const int j2 = t * 32 + lane;
        const uint2 kj = s_bits2[j2];
        const int j = 2 * j2;
        cnt += (kj.x < ki) || ((kj.x == ki) && (j     < i));
        cnt += (kj.y < ki) || ((kj.y == ki) && (j + 1 < i));
    }
    const int r = __reduce_add_sync(0xffffffffu, cnt);

    if (lane == 0) {
        const float mx = means2d[2 * i];
        const float my = means2d[2 * i + 1];
        const float a  = conics[3 * i];
        const float b  = conics[3 * i + 1];
        const float c  = conics[3 * i + 2];
        const float op = opac[i];

        // alpha = op*exp(-sigma) >= 1/255  <=>  sigma <= ln(255*op) = smax
        const float smax = logf(op * 255.0f);
        const float det  = a * c - b * b;

        d_A[r] = make_float4(mx, my, 0.5f * a, b);
        d_B[r] = make_float4(0.5f * c, smax, op, colors[3 * i]);
        d_C[r] = make_float2(colors[3 * i + 1], colors[3 * i + 2]);

        float4 bb;
        if (smax > 0.0f && det > 0.0f) {
            const float rx = sqrtf(fmaxf(0.0f, 2.0f * smax * c / det)) * 1.001f + 0.01f;
            const float ry = sqrtf(fmaxf(0.0f, 2.0f * smax * a / det)) * 1.001f + 0.01f;
            bb = make_float4(mx - rx, my - ry, mx + rx, my + ry);
        } else {
            bb = make_float4(1e9f, 1e9f, -1e9f, -1e9f);
        }
        d_bbox[r] = bb;
    }
}

// ---------------------------------------------------------------------------
// Exact (conservative) ellipse-vs-rect: keep iff min over rect of
// sigma(p) = A2*dx^2 + b*dx*dy + C2*dy^2  is <= smax (+margin).
// Min is 0 if mean inside rect, else attained on one of the 4 edges
// (1D quadratic, clamped vertex).
// ---------------------------------------------------------------------------
__device__ __forceinline__ bool ellipse_hits_rect(
    float mx, float my, float A2, float b, float C2, float smax,
    float X0, float X1, float Y0, float Y1)
{
    if (mx >= X0 && mx <= X1 && my >= Y0 && my <= Y1) return true;
    const float dx0 = X0 - mx, dx1 = X1 - mx;
    const float dy0 = Y0 - my, dy1 = Y1 - my;
    // vertex factors: y*(x) = -b*x/(2*C2), x*(y) = -b*y/(2*A2)
    const float fy = __fdividef(-b, 2.0f * C2);
    const float fx = __fdividef(-b, 2.0f * A2);

    float q = 3.4e38f;
    {   // edge x = X0
        const float y = fminf(fmaxf(fy * dx0, dy0), dy1);
        q = fminf(q, A2 * dx0 * dx0 + b * dx0 * y + C2 * y * y);
    }
    {   // edge x = X1
        const float y = fminf(fmaxf(fy * dx1, dy0), dy1);
        q = fminf(q, A2 * dx1 * dx1 + b * dx1 * y + C2 * y * y);
    }
    {   // edge y = Y0
        const float x = fminf(fmaxf(fx * dy0, dx0), dx1);
        q = fminf(q, A2 * x * x + b * x * dy0 + C2 * dy0 * dy0);
    }
    {   // edge y = Y1
        const float x = fminf(fmaxf(fx * dy1, dx0), dx1);
        q = fminf(q, A2 * x * x + b * x * dy1 + C2 * dy1 * dy1);
    }
    return q <= smax + 1e-2f;    // conservative margin (over-keep only)
}

// ---------------------------------------------------------------------------
// Kernel 2: tile raster. 16x16 tile per block (grid 32x32), 128 threads,
// 2 pixels/thread (rows ly and ly+8, same column -> shared dx).
// Per 256-gaussian chunk: bbox cull + exact ellipse-rect cull ->
// order-preserving ballot compaction (2 candidates/thread) -> sequential
// front-to-back compositing. Exact early exit at T < 1e-4.
// ---------------------------------------------------------------------------
__global__ __launch_bounds__(TPB) void raster_kernel(float* __restrict__ out)
{
    const int tileX = blockIdx.x, tileY = blockIdx.y;
    const int tid   = threadIdx.x;
    const int lx    = tid & (TILE - 1);
    const int ly    = tid >> 4;                    // 0..7
    const float px  = (float)(tileX * TILE + lx) + 0.5f;
    const float py1 = (float)(tileY * TILE + ly) + 0.5f;
    const float py2 = py1 + 8.0f;
    // pixel-center rect of this tile (for culling)
    const float X0 = (float)(tileX * TILE) + 0.5f;
    const float X1 = X0 + (float)(TILE - 1);
    const float Y0 = (float)(tileY * TILE) + 0.5f;
    const float Y1 = Y0 + (float)(TILE - 1);

    __shared__ float4 s_A[CHUNK];
    __shared__ float4 s_B[CHUNK];
    __shared__ float2 s_C[CHUNK];
    __shared__ int4   s_wcnt4[2];                  // 8 per-warp-half counts

    const int warp = tid >> 5, lane = tid & 31;    // warp 0..3
    const unsigned below = (1u << lane) - 1u;

    float T1 = 1.0f, T2 = 1.0f;
    float r1 = 0.f, g1 = 0.f, b1 = 0.f;
    float r2 = 0.f, g2 = 0.f, b2 = 0.f;
    bool done1 = false, done2 = false;

    for (int base = 0; base < G_N; base += CHUNK) {
        // ---- cull two candidates: giA (first half), giB (second half) ----
        const int giA = base + tid;
        const int giB = giA + TPB;

        float4 Aa, Ba; float2 Ca;
        bool hA = false;
        {
            const float4 bb = d_bbox[giA];
            if (bb.x <= X1 && bb.z >= X0 && bb.y <= Y1 && bb.w >= Y0) {
                Aa = d_A[giA]; Ba = d_B[giA];
                hA = ellipse_hits_rect(Aa.x, Aa.y, Aa.z, Aa.w, Ba.x, Ba.y,
                                       X0, X1, Y0, Y1);
                if (hA) Ca = d_C[giA];
            }
        }
        float4 Ab, Bb; float2 Cb;
        bool hB = false;
        {
            const float4 bb = d_bbox[giB];
            if (bb.x <= X1 && bb.z >= X0 && bb.y <= Y1 && bb.w >= Y0) {
                Ab = d_A[giB]; Bb = d_B[giB];
                hB = ellipse_hits_rect(Ab.x, Ab.y, Ab.z, Ab.w, Bb.x, Bb.y,
                                       X0, X1, Y0, Y1);
                if (hB) Cb = d_C[giB];
            }
        }

        const unsigned mA = __ballot_sync(0xffffffffu, hA);
        const unsigned mB = __ballot_sync(0xffffffffu, hB);
        if (lane == 0) {
            ((int*)s_wcnt4)[warp]     = __popc(mA);
            ((int*)s_wcnt4)[warp + 4] = __popc(mB);
        }
        __syncthreads();

        const int4 c0 = s_wcnt4[0];
        const int4 c1 = s_wcnt4[1];
        const int sumFirst = c0.x + c0.y + c0.z + c0.w;
        const int cnt = sumFirst + c1.x + c1.y + c1.z + c1.w;
        // exclusive prefix for this warp's first-half / second-half groups
        int preA = 0;
        if (warp > 0) preA += c0.x;
        if (warp > 1) preA += c0.y;
        if (warp > 2) preA += c0.z;
        int preB = sumFirst;
        if (warp > 0) preB += c1.x;
        if (warp > 1) preB += c1.y;
        if (warp > 2) preB += c1.z;

        if (hA) {
            const int slot = preA + __popc(mA & below);
            s_A[slot] = Aa; s_B[slot] = Ba; s_C[slot] = Ca;
        }
        if (hB) {
            const int slot = preB + __popc(mB & below);
            s_A[slot] = Ab; s_B[slot] = Bb; s_C[slot] = Cb;
        }
        __syncthreads();

        // ---- composite (depth order preserved) ----
        if (!(done1 && done2)) {
            for (int j = 0; j < cnt; ++j) {
                const float4 A = s_A[j];              // mx, my, a/2, b
                const float4 B = s_B[j];              // c/2, smax, op, col.r
                const float dx  = px  - A.x;
                const float dy1 = py1 - A.y;
                const float dy2 = py2 - A.y;
                const float u = A.z * dx * dx;        // (a/2)dx^2
                const float v = A.w * dx;             // b*dx
                const float s1 = fmaf(B.x * dy1, dy1, fmaf(v, dy1, u));
                const float s2 = fmaf(B.x * dy2, dy2, fmaf(v, dy2, u));
                const bool p1 = (s1 >= 0.0f) && (s1 <= B.y) && !done1;
                const bool p2 = (s2 >= 0.0f) && (s2 <= B.y) && !done2;
                if (p1 | p2) {
                    const float2 C = s_C[j];
                    if (p1) {
                        const float alpha = fminf(0.99f, B.z * __expf(-s1));
                        const float w = alpha * T1;
                        r1 += w * B.w; g1 += w * C.x; b1 += w * C.y;
                        T1 *= (1.0f - alpha);
                        done1 = (T1 < 1e-4f);
                    }
                    if (p2) {
                        const float alpha = fminf(0.99f, B.z * __expf(-s2));
                        const float w = alpha * T2;
                        r2 += w * B.w; g2 += w * C.x; b2 += w * C.y;
                        T2 *= (1.0f - alpha);
                        done2 = (T2 < 1e-4f);
                    }
                    if (done1 && done2) break;
                }
            }
        }

        const int active = __syncthreads_count((done1 && done2) ? 0 : 1);
        if (active == 0) break;
    }

    const int x  = tileX * TILE + lx;
    const int y1 = tileY * TILE + ly;
    float* o1 = out + ((size_t)y1 * IMG_W + x) * 3;
    o1[0] = r1; o1[1] = g1; o1[2] = b1;
    float* o2 = out + ((size_t)(y1 + 8) * IMG_W + x) * 3;
    o2[0] = r2; o2[1] = g2; o2[2] = b2;
}

// ---------------------------------------------------------------------------
extern "C" void kernel_launch(void* const* d_in, const int* in_sizes, int n_in,
                              void* d_out, int out_size)
{
    const float* means2d   = (const float*)d_in[0];
    const float* conics    = (const float*)d_in[1];
    const float* colors    = (const float*)d_in[2];
    const float* opacities = (const float*)d_in[3];
    const float* depths    = (const float*)d_in[4];
    float* out = (float*)d_out;

    sort_gather_kernel<<<G_N / SORT_WPB, SORT_TPB>>>(means2d, conics, colors, opacities, depths);
    dim3 grid(IMG_W / TILE, IMG_H / TILE);
    raster_kernel<<<grid, TPB>>>(out);
}

// round 4
// speedup vs baseline: 1.8043x; 1.0465x over previous
#include <cuda_runtime.h>

#define G_N 8192
#define IMG_W 512
#define IMG_H 512
#define TILE 16
#define TX_N (IMG_W / TILE)       // 32 tiles per row
#define TY_N (IMG_H / TILE)       // 32 tile rows
#define N_TILES (TX_N * TY_N)     // 1024
#define NWORDS (G_N / 32)         // 256 bitmap words per tile
#define NSUM (NWORDS / 32)        // 8 summary words per tile
#define TPB 256
#define SORT_TPB 256
#define SORT_WPB 8                // warps per block in sort kernel

// Sorted (by depth) gaussian data, raster-ready layout.
__device__ float4 d_A[G_N];              // mx, my, 0.5*a, b
__device__ float4 d_B[G_N];              // 0.5*c, sigma_max=ln(255*op), op, col.r
__device__ float2 d_C[G_N];              // col.g, col.b
__device__ float4 d_bbox[G_N];           // x0, y0, x1, y1 (conservative footprint)
// Per-tile rank bitmaps: bit r set => sorted gaussian r overlaps the tile.
__device__ unsigned d_bits[N_TILES * NWORDS];   // 1 MB
__device__ unsigned d_sum [N_TILES * NSUM];     // 32 KB (word-level summary)

// ---------------------------------------------------------------------------
// Kernel 0: clear bitmaps. 1024 blocks x 256 threads = exactly NWORDS*N_TILES.
// ---------------------------------------------------------------------------
__global__ __launch_bounds__(TPB) void clear_kernel()
{
    const int i = blockIdx.x * TPB + threadIdx.x;
    d_bits[i] = 0u;
    if (i < N_TILES * NSUM) d_sum[i] = 0u;
}

// ---------------------------------------------------------------------------
// Kernel 1: stable rank-sort by depth + gather + bbox. One warp per gaussian.
// Composite key (depth_bits, index) reproduces argsort(stable=True) exactly.
// ---------------------------------------------------------------------------
__global__ __launch_bounds__(SORT_TPB) void sort_gather_kernel(
    const float* __restrict__ means2d,
    const float* __restrict__ conics,
    const float* __restrict__ colors,
    const float* __restrict__ opac,
    const float* __restrict__ depths)
{
    __shared__ uint2 s_bits2[G_N / 2];   // 32 KB
    const int tid  = threadIdx.x;
    const int warp = tid >> 5, lane = tid & 31;

    const uint2* dbits = (const uint2*)depths;
    for (int j = tid; j < G_N / 2; j += SORT_TPB)
        s_bits2[j] = dbits[j];
    __syncthreads();

    const int i = blockIdx.x * SORT_WPB + warp;
    const unsigned ki = ((const unsigned*)s_bits2)[i];

    int cnt = 0;
#pragma unroll 8
    for (int t = 0; t < G_N / 64; ++t) {
        const int j2 = t * 32 + lane;
        const uint2 kj = s_bits2[j2];
        const int j = 2 * j2;
        cnt += (kj.x < ki) || ((kj.x == ki) && (j     < i));
        cnt += (kj.y < ki) || ((kj.y == ki) && (j + 1 < i));
    }
    const int r = __reduce_add_sync(0xffffffffu, cnt);

    if (lane == 0) {
        const float mx = means2d[2 * i];
        const float my = means2d[2 * i + 1];
        const float a  = conics[3 * i];
        const float b  = conics[3 * i + 1];
        const float c  = conics[3 * i + 2];
        const float op = opac[i];

        // alpha = op*exp(-sigma) >= 1/255  <=>  sigma <= ln(255*op) = smax
        const float smax = logf(op * 255.0f);
        const float det  = a * c - b * b;

        d_A[r] = make_float4(mx, my, 0.5f * a, b);
        d_B[r] = make_float4(0.5f * c, smax, op, colors[3 * i]);
        d_C[r] = make_float2(colors[3 * i + 1], colors[3 * i + 2]);

        float4 bb;
        if (smax > 0.0f && det > 0.0f) {
            const float rx = sqrtf(fmaxf(0.0f, 2.0f * smax * c / det)) * 1.001f + 0.01f;
            const float ry = sqrtf(fmaxf(0.0f, 2.0f * smax * a / det)) * 1.001f + 0.01f;
            bb = make_float4(mx - rx, my - ry, mx + rx, my + ry);
        } else {
            bb = make_float4(1e9f, 1e9f, -1e9f, -1e9f);
        }
        d_bbox[r] = bb;
    }
}

// ---------------------------------------------------------------------------
// Exact (conservative) ellipse-vs-rect: keep iff min over rect of
// sigma(p) = A2*dx^2 + b*dx*dy + C2*dy^2 is <= smax (+margin).
// ---------------------------------------------------------------------------
__device__ __forceinline__ bool ellipse_hits_rect(
    float mx, float my, float A2, float b, float C2, float smax,
    float X0, float X1, float Y0, float Y1)
{
    if (mx >= X0 && mx <= X1 && my >= Y0 && my <= Y1) return true;
    const float dx0 = X0 - mx, dx1 = X1 - mx;
    const float dy0 = Y0 - my, dy1 = Y1 - my;
    const float fy = __fdividef(-b, 2.0f * C2);
    const float fx = __fdividef(-b, 2.0f * A2);

    float q = 3.4e38f;
    {   const float y = fminf(fmaxf(fy * dx0, dy0), dy1);
        q = fminf(q, A2 * dx0 * dx0 + b * dx0 * y + C2 * y * y); }
    {   const float y = fminf(fmaxf(fy * dx1, dy0), dy1);
        q = fminf(q, A2 * dx1 * dx1 + b * dx1 * y + C2 * y * y); }
    {   const float x = fminf(fmaxf(fx * dy0, dx0), dx1);
        q = fminf(q, A2 * x * x + b * x * dy0 + C2 * dy0 * dy0); }
    {   const float x = fminf(fmaxf(fx * dy1, dx0), dx1);
        q = fminf(q, A2 * x * x + b * x * dy1 + C2 * dy1 * dy1); }
    return q <= smax + 1e-2f;    // conservative margin (over-keep only)
}

// ---------------------------------------------------------------------------
// Kernel 2: binning. One warp per sorted gaussian r; lanes split the covered
// tile range. Sets bit r in each overlapped tile's bitmap (+ summary bit).
// atomicOr is order-independent -> deterministic.
// ---------------------------------------------------------------------------
__global__ __launch_bounds__(TPB) void binning_kernel()
{
    const int r    = blockIdx.x * (TPB / 32) + (threadIdx.x >> 5);
    const int lane = threadIdx.x & 31;

    const float4 bb = d_bbox[r];
    if (bb.x > bb.z) return;    // empty footprint

    // Tiles whose pixel centers [16t+0.5, 16t+15.5] can intersect [bb.x, bb.z]
    const int tx0 = max(0, __float2int_rd((bb.x - 0.5f) * (1.0f / 16.0f)));
    const int tx1 = min(TX_N - 1, __float2int_rd((bb.z - 0.5f) * (1.0f / 16.0f)));
    const int ty0 = max(0, __float2int_rd((bb.y - 0.5f) * (1.0f / 16.0f)));
    const int ty1 = min(TY_N - 1, __float2int_rd((bb.w - 0.5f) * (1.0f / 16.0f)));
    if (tx1 < tx0 || ty1 < ty0) return;

    const int W = tx1 - tx0 + 1;
    const int n = W * (ty1 - ty0 + 1);

    const float4 A = d_A[r];    // mx, my, a/2, b
    const float4 B = d_B[r];    // c/2, smax, op, col.r

    for (int t = lane; t < n; t += 32) {
        const int tx = tx0 + t % W;
        const int ty = ty0 + t / W;
        const float X0 = (float)(tx * TILE) + 0.5f;
        const float Y0 = (float)(ty * TILE) + 0.5f;
        if (ellipse_hits_rect(A.x, A.y, A.z, A.w, B.x, B.y,
                              X0, X0 + (float)(TILE - 1),
                              Y0, Y0 + (float)(TILE - 1))) {
            const int tile = ty * TX_N + tx;
            atomicOr(&d_bits[tile * NWORDS + (r >> 5)], 1u << (r & 31));
            atomicOr(&d_sum [tile * NSUM  + (r >> 10)], 1u << ((r >> 5) & 31));
        }
    }
}

// ---------------------------------------------------------------------------
// Kernel 3: raster. One 16x16 tile per block, 1 px/thread, 256 threads.
// Walk the tile's rank bitmap (ascending rank = depth order), composite,
// exact early exit at T < 1e-4 checked block-wide every 32 ranks.
// ---------------------------------------------------------------------------
__global__ __launch_bounds__(TPB) void raster_kernel(float* __restrict__ out)
{
    const int tileX = blockIdx.x, tileY = blockIdx.y;
    const int tileI = tileY * TX_N + tileX;
    const int tid   = threadIdx.x;
    const int lx    = tid & (TILE - 1);
    const int ly    = tid >> 4;
    const float px  = (float)(tileX * TILE + lx) + 0.5f;
    const float py  = (float)(tileY * TILE + ly) + 0.5f;

    __shared__ unsigned s_w[NWORDS];
    __shared__ unsigned s_s[NSUM];

    s_w[tid] = d_bits[tileI * NWORDS + tid];
    if (tid < NSUM) s_s[tid] = d_sum[tileI * NSUM + tid];
    __syncthreads();

    float T = 1.0f;
    float aR = 0.0f, aG = 0.0f, aB = 0.0f;
    bool done = false;
    int since = 0;

#pragma unroll 1
    for (int sw = 0; sw < NSUM; ++sw) {
        unsigned sm = s_s[sw];
        while (sm) {
            const int wb = __ffs(sm) - 1;
            sm &= sm - 1;
            const int wi = sw * 32 + wb;
            unsigned bits = s_w[wi];
            while (bits) {
                const int rb = __ffs(bits) - 1;
                bits &= bits - 1;
                const int r = wi * 32 + rb;

                if (!done) {
                    const float4 A = __ldg(&d_A[r]);   // broadcast (same addr/warp)
                    const float4 B = __ldg(&d_B[r]);
                    const float dx = px - A.x;
                    const float dy = py - A.y;
                    const float sg = fmaf(A.z * dx, dx,
                                     fmaf(B.x * dy, dy, A.w * dx * dy));
                    if (sg >= 0.0f && sg <= B.y) {
                        const float2 C = __ldg(&d_C[r]);
                        const float alpha = fminf(0.99f, B.z * __expf(-sg));
                        const float w = alpha * T;
                        aR += w * B.w; aG += w * C.x; aB += w * C.y;
                        T *= (1.0f - alpha);
                        done = (T < 1e-4f);
                    }
                }
                // Uniform across block (bit sequence comes from shared memory).
                if (++since >= 32) {
                    since = 0;
                    if (__syncthreads_count(done ? 0 : 1) == 0) goto writeout;
                }
            }
        }
    }

writeout:
    float* o = out + ((size_t)(tileY * TILE + ly) * IMG_W + (tileX * TILE + lx)) * 3;
    o[0] = aR;
    o[1] = aG;
    o[2] = aB;
}

// ---------------------------------------------------------------------------
extern "C" void kernel_launch(void* const* d_in, const int* in_sizes, int n_in,
                              void* d_out, int out_size)
{
    const float* means2d   = (const float*)d_in[0];
    const float* conics    = (const float*)d_in[1];
    const float* colors    = (const float*)d_in[2];
    const float* opacities = (const float*)d_in[3];
    const float* depths    = (const float*)d_in[4];
    float* out = (float*)d_out;

    clear_kernel<<<N_TILES, TPB>>>();
    sort_gather_kernel<<<G_N / SORT_WPB, SORT_TPB>>>(means2d, conics, colors, opacities, depths);
    binning_kernel<<<G_N / (TPB / 32), TPB>>>();
    dim3 grid(TX_N, TY_N);
    raster_kernel<<<grid, TPB>>>(out);
}

// round 5
// speedup vs baseline: 2.1554x; 1.1946x over previous
#include <cuda_runtime.h>

#define G_N 8192
#define IMG_W 512
#define IMG_H 512
#define TILE 16
#define TX_N (IMG_W / TILE)       // 32
#define TY_N (IMG_H / TILE)       // 32
#define N_TILES (TX_N * TY_N)     // 1024
#define NWORDS (G_N / 32)         // 256 bitmap words per tile
#define TPB 256
#define SORT_TPB 256
#define SORT_WPB 8                // warps per block (one gaussian per warp)

// Sorted (by depth) gaussian data, raster-ready layout.
__device__ float4 d_A[G_N];              // mx, my, 0.5*a, b
__device__ float4 d_B[G_N];              // 0.5*c, sigma_max=ln(255*op), op, col.r
__device__ float2 d_C[G_N];              // col.g, col.b
__device__ float4 d_bbox[G_N];           // x0, y0, x1, y1
// Per-tile rank bitmaps: bit r set => sorted gaussian r overlaps the tile.
__device__ unsigned d_bits[N_TILES * NWORDS];   // 1 MB

// ---------------------------------------------------------------------------
// Kernel 0: clear bitmaps.
// ---------------------------------------------------------------------------
__global__ __launch_bounds__(TPB) void clear_kernel()
{
    const int i = blockIdx.x * TPB + threadIdx.x;
    ((uint4*)d_bits)[i] = make_uint4(0u, 0u, 0u, 0u);
}

// ---------------------------------------------------------------------------
// Kernel 1: stable rank-sort by depth + gather + bbox. One warp per gaussian;
// uint4 key loads (4 keys per LDS.128). Composite key (depth_bits, index)
// reproduces argsort(stable=True) exactly (positive floats -> monotone bits).
// ---------------------------------------------------------------------------
__global__ __launch_bounds__(SORT_TPB) void sort_gather_kernel(
    const float* __restrict__ means2d,
    const float* __restrict__ conics,
    const float* __restrict__ colors,
    const float* __restrict__ opac,
    const float* __restrict__ depths)
{
    __shared__ uint4 s_k4[G_N / 4];   // 32 KB
    const int tid  = threadIdx.x;
    const int warp = tid >> 5, lane = tid & 31;

    const uint4* dbits = (const uint4*)depths;
    for (int j = tid; j < G_N / 4; j += SORT_TPB)
        s_k4[j] = dbits[j];
    __syncthreads();

    const int i = blockIdx.x * SORT_WPB + warp;
    const unsigned ki = ((const unsigned*)s_k4)[i];

    int cnt = 0;
#pragma unroll 8
    for (int t = 0; t < G_N / 128; ++t) {
        const int j4 = t * 32 + lane;
        const uint4 k = s_k4[j4];
        const int j = 4 * j4;
        cnt += (k.x < ki) || ((k.x == ki) && (j     < i));
        cnt += (k.y < ki) || ((k.y == ki) && (j + 1 < i));
        cnt += (k.z < ki) || ((k.z == ki) && (j + 2 < i));
        cnt += (k.w < ki) || ((k.w == ki) && (j + 3 < i));
    }
    const int r = __reduce_add_sync(0xffffffffu, cnt);

    if (lane == 0) {
        const float mx = means2d[2 * i];
        const float my = means2d[2 * i + 1];
        const float a  = conics[3 * i];
        const float b  = conics[3 * i + 1];
        const float c  = conics[3 * i + 2];
        const float op = opac[i];

        // alpha = op*exp(-sigma) >= 1/255  <=>  sigma <= ln(255*op) = smax
        const float smax = logf(op * 255.0f);
        const float det  = a * c - b * b;

        d_A[r] = make_float4(mx, my, 0.5f * a, b);
        d_B[r] = make_float4(0.5f * c, smax, op, colors[3 * i]);
        d_C[r] = make_float2(colors[3 * i + 1], colors[3 * i + 2]);

        float4 bb;
        if (smax > 0.0f && det > 0.0f) {
            const float rx = sqrtf(fmaxf(0.0f, 2.0f * smax * c / det)) * 1.001f + 0.01f;
            const float ry = sqrtf(fmaxf(0.0f, 2.0f * smax * a / det)) * 1.001f + 0.01f;
            bb = make_float4(mx - rx, my - ry, mx + rx, my + ry);
        } else {
            bb = make_float4(1e9f, 1e9f, -1e9f, -1e9f);
        }
        d_bbox[r] = bb;
    }
}

// ---------------------------------------------------------------------------
// Exact (conservative) ellipse-vs-rect: keep iff min over rect of
// sigma(p) = A2*dx^2 + b*dx*dy + C2*dy^2 is <= smax (+margin).
// ---------------------------------------------------------------------------
__device__ __forceinline__ bool ellipse_hits_rect(
    float mx, float my, float A2, float b, float C2, float smax,
    float X0, float X1, float Y0, float Y1)
{
    if (mx >= X0 && mx <= X1 && my >= Y0 && my <= Y1) return true;
    const float dx0 = X0 - mx, dx1 = X1 - mx;
    const float dy0 = Y0 - my, dy1 = Y1 - my;
    const float fy = __fdividef(-b, 2.0f * C2);
    const float fx = __fdividef(-b, 2.0f * A2);

    float q = 3.4e38f;
    {   const float y = fminf(fmaxf(fy * dx0, dy0), dy1);
        q = fminf(q, A2 * dx0 * dx0 + b * dx0 * y + C2 * y * y); }
    {   const float y = fminf(fmaxf(fy * dx1, dy0), dy1);
        q = fminf(q, A2 * dx1 * dx1 + b * dx1 * y + C2 * y * y); }
    {   const float x = fminf(fmaxf(fx * dy0, dx0), dx1);
        q = fminf(q, A2 * x * x + b * x * dy0 + C2 * dy0 * dy0); }
    {   const float x = fminf(fmaxf(fx * dy1, dx0), dx1);
        q = fminf(q, A2 * x * x + b * x * dy1 + C2 * dy1 * dy1); }
    return q <= smax + 1e-2f;    // conservative margin (over-keep only)
}

// ---------------------------------------------------------------------------
// Kernel 2: binning. 8 lanes per gaussian (4 gaussians/warp); lanes split the
// covered tile range. atomicOr is order-independent -> deterministic.
// ---------------------------------------------------------------------------
__global__ __launch_bounds__(TPB) void binning_kernel()
{
    const int r   = (blockIdx.x * (TPB / 32) + (threadIdx.x >> 5)) * 4
                  + ((threadIdx.x >> 3) & 3);
    const int sub = threadIdx.x & 7;

    const float4 bb = d_bbox[r];
    if (bb.x > bb.z) return;

    const int tx0 = max(0, __float2int_rd((bb.x - 0.5f) * (1.0f / 16.0f)));
    const int tx1 = min(TX_N - 1, __float2int_rd((bb.z - 0.5f) * (1.0f / 16.0f)));
    const int ty0 = max(0, __float2int_rd((bb.y - 0.5f) * (1.0f / 16.0f)));
    const int ty1 = min(TY_N - 1, __float2int_rd((bb.w - 0.5f) * (1.0f / 16.0f)));
    if (tx1 < tx0 || ty1 < ty0) return;

    const int W = tx1 - tx0 + 1;
    const int n = W * (ty1 - ty0 + 1);

    const float4 A = d_A[r];    // mx, my, a/2, b
    const float4 B = d_B[r];    // c/2, smax, op, col.r

    for (int t = sub; t < n; t += 8) {
        const int tx = tx0 + t % W;
        const int ty = ty0 + t / W;
        const float X0 = (float)(tx * TILE) + 0.5f;
        const float Y0 = (float)(ty * TILE) + 0.5f;
        if (ellipse_hits_rect(A.x, A.y, A.z, A.w, B.x, B.y,
                              X0, X0 + (float)(TILE - 1),
                              Y0, Y0 + (float)(TILE - 1))) {
            const int tile = ty * TX_N + tx;
            atomicOr(&d_bits[tile * NWORDS + (r >> 5)], 1u << (r & 31));
        }
    }
}

// ---------------------------------------------------------------------------
// Kernel 3: raster. One 16x16 tile per block, 1 px/thread.
// Phase 1: bitmap -> compact uint16 rank list in shared (ascending rank ==
// depth order; popc + block prefix scan, deterministic).
// Phase 2: tight composite loop over the list; exact early exit at T < 1e-4
// checked block-wide every 32 entries.
// ---------------------------------------------------------------------------
__global__ __launch_bounds__(TPB) void raster_kernel(float* __restrict__ out)
{
    const int tileX = blockIdx.x, tileY = blockIdx.y;
    const int tileI = tileY * TX_N + tileX;
    const int tid   = threadIdx.x;
    const int warp  = tid >> 5, lane = tid & 31;
    const float px  = (float)(tileX * TILE + (tid & (TILE - 1))) + 0.5f;
    const float py  = (float)(tileY * TILE + (tid >> 4)) + 0.5f;

    __shared__ unsigned short s_list[G_N];   // 16 KB (worst case all ranks)
    __shared__ int s_wsum[8];
    __shared__ int s_cnt;

    // ---- Phase 1: build list ----
    const unsigned w = d_bits[tileI * NWORDS + tid];
    const int c = __popc(w);

    // warp inclusive scan of c
    int incl = c;
#pragma unroll
    for (int o = 1; o < 32; o <<= 1) {
        const int v = __shfl_up_sync(0xffffffffu, incl, o);
        if (lane >= o) incl += v;
    }
    if (lane == 31) s_wsum[warp] = incl;
    __syncthreads();
    int base = 0;
#pragma unroll
    for (int k = 0; k < 8; ++k) {
        const int v = s_wsum[k];
        if (k < warp) base += v;
        if (k == 7 && tid == 0) { /* nothing */ }
    }
    if (tid == 0) {
        int tot = 0;
#pragma unroll
        for (int k = 0; k < 8; ++k) tot += s_wsum[k];
        s_cnt = tot;
    }
    int ofs = base + incl - c;
    unsigned bits = w;
    const int rbase = tid << 5;
    while (bits) {
        const int rb = __ffs(bits) - 1;
        bits &= bits - 1;
        s_list[ofs++] = (unsigned short)(rbase + rb);
    }
    __syncthreads();
    const int cnt = s_cnt;

    // ---- Phase 2: composite ----
    float T = 1.0f;
    float aR = 0.0f, aG = 0.0f, aB = 0.0f;
    bool done = false;

#pragma unroll 1
    for (int j = 0; j < cnt; ++j) {
        if (!done) {
            const int r = s_list[j];
            const float4 A = __ldg(&d_A[r]);   // broadcast (same addr per warp)
            const float4 B = __ldg(&d_B[r]);
            const float dx = px - A.x;
            const float dy = py - A.y;
            const float sg = fmaf(A.z * dx, dx,
                             fmaf(B.x * dy, dy, A.w * dx * dy));
            if (sg >= 0.0f && sg <= B.y) {
                const float2 C = __ldg(&d_C[r]);
                const float alpha = fminf(0.99f, B.z * __expf(-sg));
                const float wgt = alpha * T;
                aR += wgt * B.w; aG += wgt * C.x; aB += wgt * C.y;
                T *= (1.0f - alpha);
                done = (T < 1e-4f);
            }
        }
        if (((j + 1) & 31) == 0) {
            if (__syncthreads_count(done ? 0 : 1) == 0) break;
        }
    }

    float* o = out + ((size_t)(tileY * TILE + (tid >> 4)) * IMG_W
                      + (tileX * TILE + (tid & (TILE - 1)))) * 3;
    o[0] = aR;
    o[1] = aG;
    o[2] = aB;
}

// ---------------------------------------------------------------------------
extern "C" void kernel_launch(void* const* d_in, const int* in_sizes, int n_in,
                              void* d_out, int out_size)
{
    const float* means2d   = (const float*)d_in[0];
    const float* conics    = (const float*)d_in[1];
    const float* colors    = (const float*)d_in[2];
    const float* opacities = (const float*)d_in[3];
    const float* depths    = (const float*)d_in[4];
    float* out = (float*)d_out;

    clear_kernel<<<N_TILES * NWORDS / (4 * TPB), TPB>>>();
    sort_gather_kernel<<<G_N / SORT_WPB, SORT_TPB>>>(means2d, conics, colors, opacities, depths);
    binning_kernel<<<G_N / ((TPB / 32) * 4), TPB>>>();
    dim3 grid(TX_N, TY_N);
    raster_kernel<<<grid, TPB>>>(out);
}